// round 3
// baseline (speedup 1.0000x reference)
#include <cuda_runtime.h>
#include <math.h>

#define HEADS 8
#define DHK 8
#define DHV 16
#define DIM 128
#define INC 128
#define EPS 1e-5f
#define QSCALE 0.08838834764831845f   // 128^-0.5

typedef unsigned long long ull;

__device__ float g_qkv[2048 * 256 * 128];   // [b][h][r(0..31)][d]

__device__ __forceinline__ ull pk2(float a, float b) {
    ull r; asm("mov.b64 %0, {%1, %2};" : "=l"(r) : "f"(a), "f"(b)); return r;
}
__device__ __forceinline__ void upk2(ull v, float& a, float& b) {
    asm("mov.b64 {%0, %1}, %2;" : "=f"(a), "=f"(b) : "l"(v));
}
__device__ __forceinline__ ull fma2(ull a, ull b, ull c) {
    ull r; asm("fma.rn.f32x2 %0, %1, %2, %3;" : "=l"(r) : "l"(a), "l"(b), "l"(c));
    return r;
}

// ============================================================================
// Kernel A: conv1x1 + BN (+ q pre-scale) as per-batch GEMM  (unchanged)
// ============================================================================
#define AS_STRIDE 260

__global__ void __launch_bounds__(512, 1)
conv_bn_kernel(const float* __restrict__ x, const float* __restrict__ W,
               const float* __restrict__ gamma, const float* __restrict__ beta,
               const float* __restrict__ mean, const float* __restrict__ var,
               float* __restrict__ qkv)
{
    extern __shared__ float sm[];
    float* As = sm;
    float* Bs = sm + 32 * AS_STRIDE;

    const int b  = blockIdx.x;
    const int t  = threadIdx.x;
    const int rt = t >> 4, dt = t & 15;
    const int r0 = rt * 8, d0 = dt * 8;

    ull acc[8][4];
#pragma unroll
    for (int a = 0; a < 8; ++a)
#pragma unroll
        for (int p = 0; p < 4; ++p) acc[a][p] = 0ULL;

    const float* xb = x + (size_t)b * (INC * DIM);

    for (int cc = 0; cc < 4; ++cc) {
        __syncthreads();
#pragma unroll
        for (int it = 0; it < 4; ++it) {
            int e4 = t + 512 * it;
            int o  = e4 >> 3;
            int kq = (e4 & 7) * 4;
            float4 wv = *reinterpret_cast<const float4*>(W + o * INC + cc * 32 + kq);
            As[(kq + 0) * AS_STRIDE + o] = wv.x;
            As[(kq + 1) * AS_STRIDE + o] = wv.y;
            As[(kq + 2) * AS_STRIDE + o] = wv.z;
            As[(kq + 3) * AS_STRIDE + o] = wv.w;
        }
#pragma unroll
        for (int it = 0; it < 2; ++it) {
            int e4 = t + 512 * it;
            int kq = e4 >> 5;
            int d4 = (e4 & 31) * 4;
            *reinterpret_cast<float4*>(Bs + kq * DIM + d4) =
                *reinterpret_cast<const float4*>(xb + (cc * 32 + kq) * DIM + d4);
        }
        __syncthreads();

#pragma unroll 8
        for (int kk = 0; kk < 32; ++kk) {
            const float* brow = Bs + kk * DIM + d0;
            ull x0 = *reinterpret_cast<const ull*>(brow + 0);
            ull x1 = *reinterpret_cast<const ull*>(brow + 2);
            ull x2 = *reinterpret_cast<const ull*>(brow + 4);
            ull x3 = *reinterpret_cast<const ull*>(brow + 6);
            float wv[8];
            *reinterpret_cast<float4*>(wv)     = *reinterpret_cast<const float4*>(As + kk * AS_STRIDE + r0);
            *reinterpret_cast<float4*>(wv + 4) = *reinterpret_cast<const float4*>(As + kk * AS_STRIDE + r0 + 4);
#pragma unroll
            for (int rr = 0; rr < 8; ++rr) {
                ull wp = pk2(wv[rr], wv[rr]);
                acc[rr][0] = fma2(x0, wp, acc[rr][0]);
                acc[rr][1] = fma2(x1, wp, acc[rr][1]);
                acc[rr][2] = fma2(x2, wp, acc[rr][2]);
                acc[rr][3] = fma2(x3, wp, acc[rr][3]);
            }
        }
    }

#pragma unroll
    for (int rr = 0; rr < 8; ++rr) {
        int o = r0 + rr;
        float iv   = gamma[o] * rsqrtf(var[o] + EPS);
        float bias = beta[o] - mean[o] * iv;
        if (o < 64) { iv *= QSCALE; bias *= QSCALE; }
        int r = o >> 3, h = o & 7;
        float* dst = qkv + (size_t)b * 32768 + h * 4096 + r * 128 + d0;
        float v0, v1, v2, v3, v4, v5, v6, v7;
        upk2(acc[rr][0], v0, v1); upk2(acc[rr][1], v2, v3);
        upk2(acc[rr][2], v4, v5); upk2(acc[rr][3], v6, v7);
        float4 s0, s1;
        s0.x = v0 * iv + bias; s0.y = v1 * iv + bias;
        s0.z = v2 * iv + bias; s0.w = v3 * iv + bias;
        s1.x = v4 * iv + bias; s1.y = v5 * iv + bias;
        s1.z = v6 * iv + bias; s1.w = v7 * iv + bias;
        *reinterpret_cast<float4*>(dst)     = s0;
        *reinterpret_cast<float4*>(dst + 4) = s1;
    }
}

// ============================================================================
// Kernel B: attention per (b, h) — fused exp, deferred normalization
// smem (floats):
//  q     [8][128]    @ 0      (aliased by psum[16][128] after logits)
//  k     [8][128]    @ 1024
//  vdup  [128][16]   @ 2048   (ull pairs: v[i][j] duplicated, j-major)
//  relqk [16][256]   @ 6144   (q_emb/k_emb, later relv)
//  attnT [128][132]  @ 10240  (exp'd logits, transposed; aliased by outred)
//  invs  [128]       @ 27136
// total 27264 floats = 109056 B -> 2 CTAs/SM
// ============================================================================
#define AT_STRIDE 132
#define SM_Q     0
#define SM_K     1024
#define SM_VDUP  2048
#define SM_REL   6144
#define SM_ATT   10240
#define SM_INV   27136
#define SM_TOTAL 27264

__global__ void __launch_bounds__(256, 2)
attn_kernel(const float* __restrict__ qkv, const float* __restrict__ relative,
            float* __restrict__ out)
{
    extern __shared__ float sm[];
    float* q     = sm + SM_Q;
    float* k     = sm + SM_K;
    ull*   vdup  = reinterpret_cast<ull*>(sm + SM_VDUP);
    float* relqk = sm + SM_REL;
    float* attnT = sm + SM_ATT;
    float* invs  = sm + SM_INV;
    float* psum  = sm + SM_Q;     // alias q/k after logits
    float* relv  = relqk;         // alias after logits
    float* outred = attnT;        // alias after out j-loop

    const int t   = threadIdx.x;
    const int bid = blockIdx.x;
    const int b   = bid >> 3;
    const int h   = bid & 7;

    // ---------------- phase 0: load q/k/vdup + relqk --------------------------
    {
        const float* src = qkv + (size_t)b * 32768 + h * 4096;
#pragma unroll
        for (int it = 0; it < 4; ++it) {
            int e4 = t + 256 * it;              // 0..1023
            int r  = e4 >> 5;
            int dw = (e4 & 31) * 4;
            float4 val = *reinterpret_cast<const float4*>(src + r * 128 + dw);
            if (r < 8) {
                *reinterpret_cast<float4*>(q + r * 128 + dw) = val;
            } else if (r < 16) {
                *reinterpret_cast<float4*>(k + (r - 8) * 128 + dw) = val;
            } else {
                int i = r - 16;
                vdup[(dw + 0) * 16 + i] = pk2(val.x, val.x);
                vdup[(dw + 1) * 16 + i] = pk2(val.y, val.y);
                vdup[(dw + 2) * 16 + i] = pk2(val.z, val.z);
                vdup[(dw + 3) * 16 + i] = pk2(val.w, val.w);
            }
        }
        for (int idx = t; idx < 16 * 255; idx += 256) {
            int c = idx / 255, m = idx - c * 255;
            relqk[c * 256 + m] = relative[idx];
        }
    }
    __syncthreads();

    // ---------------- phase 1: logits + exp -----------------------------------
    float sums[8];
    {
        const int tx = t & 15, ty = t >> 4;
        const int d0 = tx * 8, j0 = ty * 8;
        const int base = d0 - j0 + 120;

        ull acc[8][4];
#pragma unroll
        for (int a = 0; a < 8; ++a)
#pragma unroll
            for (int p = 0; p < 4; ++p) acc[a][p] = 0ULL;

#pragma unroll 2
        for (int i = 0; i < 8; ++i) {
            const float* qi = q + i * 128;
            const float* ki = k + i * 128;
            ull qp[4], kp[4];
            {
                ulonglong2 a0 = *reinterpret_cast<const ulonglong2*>(qi + d0);
                ulonglong2 a1 = *reinterpret_cast<const ulonglong2*>(qi + d0 + 4);
                qp[0] = a0.x; qp[1] = a0.y; qp[2] = a1.x; qp[3] = a1.y;
                ulonglong2 b0 = *reinterpret_cast<const ulonglong2*>(ki + d0);
                ulonglong2 b1 = *reinterpret_cast<const ulonglong2*>(ki + d0 + 4);
                kp[0] = b0.x; kp[1] = b0.y; kp[2] = b1.x; kp[3] = b1.y;
            }
            // dots
            {
                float kj[8];
                *reinterpret_cast<float4*>(kj)     = *reinterpret_cast<const float4*>(ki + j0);
                *reinterpret_cast<float4*>(kj + 4) = *reinterpret_cast<const float4*>(ki + j0 + 4);
#pragma unroll
                for (int jj = 0; jj < 8; ++jj) {
                    ull kk2 = pk2(kj[jj], kj[jj]);
#pragma unroll
                    for (int p = 0; p < 4; ++p)
                        acc[jj][p] = fma2(qp[p], kk2, acc[jj][p]);
                }
            }
            // qr: q[i][d] * relq[i][d-j+127]
            {
                float w[16];
                const float* rr = relqk + i * 256 + base;
#pragma unroll
                for (int u = 0; u < 4; ++u)
                    *reinterpret_cast<float4*>(w + 4 * u) = *reinterpret_cast<const float4*>(rr + 4 * u);
                ull wo[7];
#pragma unroll
                for (int u = 0; u < 7; ++u) wo[u] = pk2(w[2 * u + 1], w[2 * u + 2]);
#pragma unroll
                for (int jj = 0; jj < 8; ++jj)
#pragma unroll
                    for (int p = 0; p < 4; ++p) {
                        const int a = 2 * p + 7 - jj;
                        ull pair = (a & 1) ? wo[a >> 1]
                                           : *reinterpret_cast<const ull*>(w + a);
                        acc[jj][p] = fma2(qp[p], pair, acc[jj][p]);
                    }
            }
            // kr: k[i][d] * relk[i][d-j+127]
            {
                float w[16];
                const float* rr = relqk + (8 + i) * 256 + base;
#pragma unroll
                for (int u = 0; u < 4; ++u)
                    *reinterpret_cast<float4*>(w + 4 * u) = *reinterpret_cast<const float4*>(rr + 4 * u);
                ull wo[7];
#pragma unroll
                for (int u = 0; u < 7; ++u) wo[u] = pk2(w[2 * u + 1], w[2 * u + 2]);
#pragma unroll
                for (int jj = 0; jj < 8; ++jj)
#pragma unroll
                    for (int p = 0; p < 4; ++p) {
                        const int a = 2 * p + 7 - jj;
                        ull pair = (a & 1) ? wo[a >> 1]
                                           : *reinterpret_cast<const ull*>(w + a);
                        acc[jj][p] = fma2(kp[p], pair, acc[jj][p]);
                    }
            }
        }

        // epilogue: exp + row-sum partials + transposed store
#pragma unroll
        for (int dd = 0; dd < 8; ++dd) sums[dd] = 0.f;
#pragma unroll
        for (int jj = 0; jj < 8; ++jj) {
            float* dst = attnT + (j0 + jj) * AT_STRIDE + d0;
#pragma unroll
            for (int p = 0; p < 4; ++p) {
                float lo, hi;
                upk2(acc[jj][p], lo, hi);
                float e0 = __expf(lo), e1 = __expf(hi);
                sums[2 * p]     += e0;
                sums[2 * p + 1] += e1;
                float2 s; s.x = e0; s.y = e1;
                *reinterpret_cast<float2*>(dst + 2 * p) = s;
            }
        }
    }
    __syncthreads();   // attnT complete; q/k/relqk now dead

    // ---------------- phase 2: psum write + relv load --------------------------
    {
        const int tx = t & 15, ty = t >> 4;
        const int d0 = tx * 8;
#pragma unroll
        for (int dd = 0; dd < 8; ++dd)
            psum[ty * 128 + d0 + dd] = sums[dd];
        for (int idx = t; idx < 16 * 255; idx += 256) {
            int c = idx / 255, m = idx - c * 255;
            relv[c * 256 + m] = relative[16 * 255 + idx];
        }
    }
    __syncthreads();

    if (t < 128) {
        float s = 0.f;
#pragma unroll
        for (int ty2 = 0; ty2 < 16; ++ty2) s += psum[ty2 * 128 + t];
        invs[t] = 1.0f / s;
    }
    __syncthreads();

    // ---------------- phase 3: out + kv (j split 4 ways) ----------------------
    {
        const int jq = t >> 6;
        const int ig = (t >> 4) & 3;
        const int dg = t & 15;
        const int d0 = dg * 8;
        const int i0 = ig * 4;

        ull acc2[4][4];
#pragma unroll
        for (int ii = 0; ii < 4; ++ii)
#pragma unroll
            for (int p = 0; p < 4; ++p) acc2[ii][p] = 0ULL;

        for (int g = 0; g < 8; ++g) {
            const int jb  = jq * 32 + g * 4;
            const int mlo = d0 - jb + 124;            // in [0, 244], mult of 4

            float w[4][12];
#pragma unroll
            for (int ii = 0; ii < 4; ++ii) {
                const float* rp = relv + (i0 + ii) * 256 + mlo;
                *reinterpret_cast<float4*>(w[ii])     = *reinterpret_cast<const float4*>(rp);
                *reinterpret_cast<float4*>(w[ii] + 4) = *reinterpret_cast<const float4*>(rp + 4);
                *reinterpret_cast<float4*>(w[ii] + 8) = *reinterpret_cast<const float4*>(rp + 8);
            }

#pragma unroll
            for (int jj = 0; jj < 4; ++jj) {
                const int j = jb + jj;
                ull at[4];
                {
                    const float* arow = attnT + j * AT_STRIDE + d0;
                    ulonglong2 a0 = *reinterpret_cast<const ulonglong2*>(arow);
                    ulonglong2 a1 = *reinterpret_cast<const ulonglong2*>(arow + 4);
                    at[0] = a0.x; at[1] = a0.y; at[2] = a1.x; at[3] = a1.y;
                }
                ull vp[4];
                {
                    const ull* vrow = vdup + j * 16 + i0;
                    ulonglong2 v0 = *reinterpret_cast<const ulonglong2*>(vrow);
                    ulonglong2 v1 = *reinterpret_cast<const ulonglong2*>(vrow + 2);
                    vp[0] = v0.x; vp[1] = v0.y; vp[2] = v1.x; vp[3] = v1.y;
                }
#pragma unroll
                for (int ii = 0; ii < 4; ++ii) {
#pragma unroll
                    for (int p = 0; p < 4; ++p)
                        acc2[ii][p] = fma2(at[p], vp[ii], acc2[ii][p]);
#pragma unroll
                    for (int p = 0; p < 4; ++p) {
                        const int o = 2 * p + 3 - jj;    // 0..9
                        ull pair = (o & 1) ? pk2(w[ii][o], w[ii][o + 1])
                                           : *reinterpret_cast<const ull*>(w[ii] + o);
                        acc2[ii][p] = fma2(at[p], pair, acc2[ii][p]);
                    }
                }
            }
        }

        __syncthreads();   // all attnT reads done; outred can overwrite it

        // write partials
#pragma unroll
        for (int ii = 0; ii < 4; ++ii)
#pragma unroll
            for (int p = 0; p < 4; ++p)
                *reinterpret_cast<ull*>(outred + jq * 2048 + (i0 + ii) * 128 + d0 + 2 * p) = acc2[ii][p];
    }
    __syncthreads();

    // ---------------- phase 4: reduce, normalize, store -----------------------
    {
        const int o0 = t * 8;          // over 2048 outputs
        float4 r0 = make_float4(0.f, 0.f, 0.f, 0.f);
        float4 r1 = make_float4(0.f, 0.f, 0.f, 0.f);
#pragma unroll
        for (int jq2 = 0; jq2 < 4; ++jq2) {
            float4 a = *reinterpret_cast<const float4*>(outred + jq2 * 2048 + o0);
            float4 c = *reinterpret_cast<const float4*>(outred + jq2 * 2048 + o0 + 4);
            r0.x += a.x; r0.y += a.y; r0.z += a.z; r0.w += a.w;
            r1.x += c.x; r1.y += c.y; r1.z += c.z; r1.w += c.w;
        }
        const int drr = o0 & 127;
        const int i   = o0 >> 7;
        float4 v0 = *reinterpret_cast<const float4*>(invs + drr);
        float4 v1 = *reinterpret_cast<const float4*>(invs + drr + 4);
        r0.x *= v0.x; r0.y *= v0.y; r0.z *= v0.z; r0.w *= v0.w;
        r1.x *= v1.x; r1.y *= v1.y; r1.z *= v1.z; r1.w *= v1.w;
        float* ob = out + (size_t)b * 16384 + h * 2048;
        *reinterpret_cast<float4*>(ob + i * 128 + drr)     = r0;
        *reinterpret_cast<float4*>(ob + i * 128 + drr + 4) = r1;
    }
}

// ============================================================================
extern "C" void kernel_launch(void* const* d_in, const int* in_sizes, int n_in,
                              void* d_out, int out_size) {
    const float* x        = (const float*)d_in[0];
    const float* W        = (const float*)d_in[1];
    const float* gamma    = (const float*)d_in[2];
    const float* beta     = (const float*)d_in[3];
    const float* mean     = (const float*)d_in[4];
    const float* var      = (const float*)d_in[5];
    const float* relative = (const float*)d_in[6];
    float* out = (float*)d_out;

    int nb = in_sizes[0] / (INC * DIM);

    float* scratch;
    cudaGetSymbolAddress((void**)&scratch, g_qkv);

    const int smemA = (32 * AS_STRIDE + 32 * 128) * (int)sizeof(float);
    const int smemB = SM_TOTAL * (int)sizeof(float);
    cudaFuncSetAttribute(conv_bn_kernel, cudaFuncAttributeMaxDynamicSharedMemorySize, smemA);
    cudaFuncSetAttribute(attn_kernel,    cudaFuncAttributeMaxDynamicSharedMemorySize, smemB);

    conv_bn_kernel<<<nb, 512, smemA>>>(x, W, gamma, beta, mean, var, scratch);
    attn_kernel<<<nb * HEADS, 256, smemB>>>(scratch, relative, out);
}

// round 4
// speedup vs baseline: 1.1555x; 1.1555x over previous
#include <cuda_runtime.h>
#include <math.h>

#define HEADS 8
#define DHK 8
#define DHV 16
#define DIM 128
#define INC 128
#define EPS 1e-5f
#define QSCALE 0.08838834764831845f   // 128^-0.5

typedef unsigned long long ull;

__device__ float g_qkv[2048 * 256 * 128];   // [b][h][r(0..31)][d]

__device__ __forceinline__ ull pk2(float a, float b) {
    ull r; asm("mov.b64 %0, {%1, %2};" : "=l"(r) : "f"(a), "f"(b)); return r;
}
__device__ __forceinline__ void upk2(ull v, float& a, float& b) {
    asm("mov.b64 {%0, %1}, %2;" : "=f"(a), "=f"(b) : "l"(v));
}
__device__ __forceinline__ ull fma2(ull a, ull b, ull c) {
    ull r; asm("fma.rn.f32x2 %0, %1, %2, %3;" : "=l"(r) : "l"(a), "l"(b), "l"(c));
    return r;
}
__device__ __forceinline__ ull add2(ull a, ull b) {
    ull r; asm("add.rn.f32x2 %0, %1, %2;" : "=l"(r) : "l"(a), "l"(b));
    return r;
}

// ============================================================================
// Kernel A: conv1x1 + BN (+ q pre-scale) as per-batch GEMM  (unchanged)
// ============================================================================
#define AS_STRIDE 260

__global__ void __launch_bounds__(512, 1)
conv_bn_kernel(const float* __restrict__ x, const float* __restrict__ W,
               const float* __restrict__ gamma, const float* __restrict__ beta,
               const float* __restrict__ mean, const float* __restrict__ var,
               float* __restrict__ qkv)
{
    extern __shared__ float sm[];
    float* As = sm;
    float* Bs = sm + 32 * AS_STRIDE;

    const int b  = blockIdx.x;
    const int t  = threadIdx.x;
    const int rt = t >> 4, dt = t & 15;
    const int r0 = rt * 8, d0 = dt * 8;

    ull acc[8][4];
#pragma unroll
    for (int a = 0; a < 8; ++a)
#pragma unroll
        for (int p = 0; p < 4; ++p) acc[a][p] = 0ULL;

    const float* xb = x + (size_t)b * (INC * DIM);

    for (int cc = 0; cc < 4; ++cc) {
        __syncthreads();
#pragma unroll
        for (int it = 0; it < 4; ++it) {
            int e4 = t + 512 * it;
            int o  = e4 >> 3;
            int kq = (e4 & 7) * 4;
            float4 wv = *reinterpret_cast<const float4*>(W + o * INC + cc * 32 + kq);
            As[(kq + 0) * AS_STRIDE + o] = wv.x;
            As[(kq + 1) * AS_STRIDE + o] = wv.y;
            As[(kq + 2) * AS_STRIDE + o] = wv.z;
            As[(kq + 3) * AS_STRIDE + o] = wv.w;
        }
#pragma unroll
        for (int it = 0; it < 2; ++it) {
            int e4 = t + 512 * it;
            int kq = e4 >> 5;
            int d4 = (e4 & 31) * 4;
            *reinterpret_cast<float4*>(Bs + kq * DIM + d4) =
                *reinterpret_cast<const float4*>(xb + (cc * 32 + kq) * DIM + d4);
        }
        __syncthreads();

#pragma unroll 8
        for (int kk = 0; kk < 32; ++kk) {
            const float* brow = Bs + kk * DIM + d0;
            ull x0 = *reinterpret_cast<const ull*>(brow + 0);
            ull x1 = *reinterpret_cast<const ull*>(brow + 2);
            ull x2 = *reinterpret_cast<const ull*>(brow + 4);
            ull x3 = *reinterpret_cast<const ull*>(brow + 6);
            float wv[8];
            *reinterpret_cast<float4*>(wv)     = *reinterpret_cast<const float4*>(As + kk * AS_STRIDE + r0);
            *reinterpret_cast<float4*>(wv + 4) = *reinterpret_cast<const float4*>(As + kk * AS_STRIDE + r0 + 4);
#pragma unroll
            for (int rr = 0; rr < 8; ++rr) {
                ull wp = pk2(wv[rr], wv[rr]);
                acc[rr][0] = fma2(x0, wp, acc[rr][0]);
                acc[rr][1] = fma2(x1, wp, acc[rr][1]);
                acc[rr][2] = fma2(x2, wp, acc[rr][2]);
                acc[rr][3] = fma2(x3, wp, acc[rr][3]);
            }
        }
    }

#pragma unroll
    for (int rr = 0; rr < 8; ++rr) {
        int o = r0 + rr;
        float iv   = gamma[o] * rsqrtf(var[o] + EPS);
        float bias = beta[o] - mean[o] * iv;
        if (o < 64) { iv *= QSCALE; bias *= QSCALE; }
        int r = o >> 3, h = o & 7;
        float* dst = qkv + (size_t)b * 32768 + h * 4096 + r * 128 + d0;
        float v0, v1, v2, v3, v4, v5, v6, v7;
        upk2(acc[rr][0], v0, v1); upk2(acc[rr][1], v2, v3);
        upk2(acc[rr][2], v4, v5); upk2(acc[rr][3], v6, v7);
        float4 s0, s1;
        s0.x = v0 * iv + bias; s0.y = v1 * iv + bias;
        s0.z = v2 * iv + bias; s0.w = v3 * iv + bias;
        s1.x = v4 * iv + bias; s1.y = v5 * iv + bias;
        s1.z = v6 * iv + bias; s1.w = v7 * iv + bias;
        *reinterpret_cast<float4*>(dst)     = s0;
        *reinterpret_cast<float4*>(dst + 4) = s1;
    }
}

// ============================================================================
// Kernel B: attention per (b, h)
// ============================================================================
#define AT_STRIDE 132
#define SM_Q     0
#define SM_K     1024
#define SM_VDUP  2048
#define SM_REL   6144
#define SM_ATT   10240
#define SM_INV   27136
#define SM_TOTAL 27264

__global__ void __launch_bounds__(256, 2)
attn_kernel(const float* __restrict__ qkv, const float* __restrict__ relative,
            float* __restrict__ out)
{
    extern __shared__ float sm[];
    float* q     = sm + SM_Q;
    float* k     = sm + SM_K;
    ull*   vdup  = reinterpret_cast<ull*>(sm + SM_VDUP);
    float* relqk = sm + SM_REL;
    float* attnT = sm + SM_ATT;
    float* invs  = sm + SM_INV;
    float* psum  = sm + SM_Q;     // alias q/k after logits
    float* relv  = relqk;         // alias after logits

    const int t   = threadIdx.x;
    const int bid = blockIdx.x;
    const int b   = bid >> 3;
    const int h   = bid & 7;

    // ---------------- phase 0: load q/k/vdup + relqk --------------------------
    {
        const float* src = qkv + (size_t)b * 32768 + h * 4096;
#pragma unroll
        for (int it = 0; it < 4; ++it) {
            int e4 = t + 256 * it;              // 0..1023
            int r  = e4 >> 5;
            int dw = (e4 & 31) * 4;
            float4 val = *reinterpret_cast<const float4*>(src + r * 128 + dw);
            if (r < 8) {
                *reinterpret_cast<float4*>(q + r * 128 + dw) = val;
            } else if (r < 16) {
                *reinterpret_cast<float4*>(k + (r - 8) * 128 + dw) = val;
            } else {
                int i = r - 16;
                vdup[(dw + 0) * 16 + i] = pk2(val.x, val.x);
                vdup[(dw + 1) * 16 + i] = pk2(val.y, val.y);
                vdup[(dw + 2) * 16 + i] = pk2(val.z, val.z);
                vdup[(dw + 3) * 16 + i] = pk2(val.w, val.w);
            }
        }
        for (int idx = t; idx < 16 * 255; idx += 256) {
            int c = idx / 255, m = idx - c * 255;
            relqk[c * 256 + m] = relative[idx];
        }
    }
    __syncthreads();

    // ---------------- phase 1: logits + exp -----------------------------------
    float sums[8];
    {
        const int tx = t & 15, ty = t >> 4;
        const int d0 = tx * 8, j0 = ty * 8;
        const int base = d0 - j0 + 120;

        ull acc[8][4];
#pragma unroll
        for (int a = 0; a < 8; ++a)
#pragma unroll
            for (int p = 0; p < 4; ++p) acc[a][p] = 0ULL;

#pragma unroll 2
        for (int i = 0; i < 8; ++i) {
            const float* qi = q + i * 128;
            const float* ki = k + i * 128;
            ull qp[4], kp[4];
            {
                ulonglong2 a0 = *reinterpret_cast<const ulonglong2*>(qi + d0);
                ulonglong2 a1 = *reinterpret_cast<const ulonglong2*>(qi + d0 + 4);
                qp[0] = a0.x; qp[1] = a0.y; qp[2] = a1.x; qp[3] = a1.y;
                ulonglong2 b0 = *reinterpret_cast<const ulonglong2*>(ki + d0);
                ulonglong2 b1 = *reinterpret_cast<const ulonglong2*>(ki + d0 + 4);
                kp[0] = b0.x; kp[1] = b0.y; kp[2] = b1.x; kp[3] = b1.y;
            }
            // dots
            {
                float kj[8];
                *reinterpret_cast<float4*>(kj)     = *reinterpret_cast<const float4*>(ki + j0);
                *reinterpret_cast<float4*>(kj + 4) = *reinterpret_cast<const float4*>(ki + j0 + 4);
#pragma unroll
                for (int jj = 0; jj < 8; ++jj) {
                    ull kk2 = pk2(kj[jj], kj[jj]);
#pragma unroll
                    for (int p = 0; p < 4; ++p)
                        acc[jj][p] = fma2(qp[p], kk2, acc[jj][p]);
                }
            }
            // qr
            {
                float w[16];
                const float* rr = relqk + i * 256 + base;
#pragma unroll
                for (int u = 0; u < 4; ++u)
                    *reinterpret_cast<float4*>(w + 4 * u) = *reinterpret_cast<const float4*>(rr + 4 * u);
                ull wo[7];
#pragma unroll
                for (int u = 0; u < 7; ++u) wo[u] = pk2(w[2 * u + 1], w[2 * u + 2]);
#pragma unroll
                for (int jj = 0; jj < 8; ++jj)
#pragma unroll
                    for (int p = 0; p < 4; ++p) {
                        const int a = 2 * p + 7 - jj;
                        ull pair = (a & 1) ? wo[a >> 1]
                                           : *reinterpret_cast<const ull*>(w + a);
                        acc[jj][p] = fma2(qp[p], pair, acc[jj][p]);
                    }
            }
            // kr
            {
                float w[16];
                const float* rr = relqk + (8 + i) * 256 + base;
#pragma unroll
                for (int u = 0; u < 4; ++u)
                    *reinterpret_cast<float4*>(w + 4 * u) = *reinterpret_cast<const float4*>(rr + 4 * u);
                ull wo[7];
#pragma unroll
                for (int u = 0; u < 7; ++u) wo[u] = pk2(w[2 * u + 1], w[2 * u + 2]);
#pragma unroll
                for (int jj = 0; jj < 8; ++jj)
#pragma unroll
                    for (int p = 0; p < 4; ++p) {
                        const int a = 2 * p + 7 - jj;
                        ull pair = (a & 1) ? wo[a >> 1]
                                           : *reinterpret_cast<const ull*>(w + a);
                        acc[jj][p] = fma2(kp[p], pair, acc[jj][p]);
                    }
            }
        }

        // epilogue: exp + row-sum partials + transposed store
#pragma unroll
        for (int dd = 0; dd < 8; ++dd) sums[dd] = 0.f;
#pragma unroll
        for (int jj = 0; jj < 8; ++jj) {
            float* dst = attnT + (j0 + jj) * AT_STRIDE + d0;
#pragma unroll
            for (int p = 0; p < 4; ++p) {
                float lo, hi;
                upk2(acc[jj][p], lo, hi);
                float e0 = __expf(lo), e1 = __expf(hi);
                sums[2 * p]     += e0;
                sums[2 * p + 1] += e1;
                float2 s; s.x = e0; s.y = e1;
                *reinterpret_cast<float2*>(dst + 2 * p) = s;
            }
        }
    }
    __syncthreads();   // attnT complete; q/k/relqk dead

    // ---------------- phase 2: psum + relv load + invs -------------------------
    {
        const int tx = t & 15, ty = t >> 4;
        const int d0 = tx * 8;
#pragma unroll
        for (int dd = 0; dd < 8; ++dd)
            psum[ty * 128 + d0 + dd] = sums[dd];
        for (int idx = t; idx < 16 * 255; idx += 256) {
            int c = idx / 255, m = idx - c * 255;
            relv[c * 256 + m] = relative[16 * 255 + idx];
        }
    }
    __syncthreads();
    if (t < 128) {
        float s = 0.f;
#pragma unroll
        for (int ty2 = 0; ty2 < 16; ++ty2) s += psum[ty2 * 128 + t];
        invs[t] = 1.0f / s;
    }
    __syncthreads();

    // ---------------- phase 3: out + kv ----------------------------------------
    // warp = (jh in {0,1}) x (ig in 0..3); lane -> d0 = lane*4
    // sliding Toeplitz window per i: staggered ull pairs we[3] (even offsets
    // 0,2,4) / wo[3] (odd offsets 1,3,5), shifted by 4 floats per 4-j step.
    {
        const int lane = t & 31;
        const int wd   = t >> 5;
        const int i0   = (wd & 3) * 4;
        const int jh   = wd >> 2;
        const int d0   = lane * 4;
        const int jb0  = jh * 64;

        ull acc[4][2];
#pragma unroll
        for (int ii = 0; ii < 4; ++ii) { acc[ii][0] = 0ULL; acc[ii][1] = 0ULL; }

        ull we[4][3], wo[4][3];
        float lastf0[4];

        // init windows at base0 = d0 - jb0 + 124 (covers offsets 0..7)
#pragma unroll
        for (int ii = 0; ii < 4; ++ii) {
            const float* rp = relv + (i0 + ii) * 256 + (d0 - jb0 + 124);
            float4 lo4 = *reinterpret_cast<const float4*>(rp);
            float4 hi4 = *reinterpret_cast<const float4*>(rp + 4);
            we[ii][0] = pk2(lo4.x, lo4.y);
            we[ii][1] = pk2(lo4.z, lo4.w);
            we[ii][2] = pk2(hi4.x, hi4.y);
            wo[ii][0] = pk2(lo4.y, lo4.z);
            wo[ii][1] = pk2(lo4.w, hi4.x);
            wo[ii][2] = pk2(hi4.y, hi4.z);
            lastf0[ii] = lo4.x;
        }

        for (int g = 0; g < 16; ++g) {
            const int jb = jb0 + g * 4;
            if (g > 0) {
                const int baseg = d0 - jb + 124;
#pragma unroll
                for (int ii = 0; ii < 4; ++ii) {
                    we[ii][2] = we[ii][0];
                    wo[ii][2] = wo[ii][0];
                    float4 f = *reinterpret_cast<const float4*>(relv + (i0 + ii) * 256 + baseg);
                    we[ii][0] = pk2(f.x, f.y);
                    we[ii][1] = pk2(f.z, f.w);
                    wo[ii][0] = pk2(f.y, f.z);
                    wo[ii][1] = pk2(f.w, lastf0[ii]);
                    lastf0[ii] = f.x;
                }
            }
#pragma unroll
            for (int jj = 0; jj < 4; ++jj) {
                const int j = jb + jj;
                ulonglong2 at2 = *reinterpret_cast<const ulonglong2*>(attnT + j * AT_STRIDE + d0);
                const ull* vr = vdup + j * 16 + i0;
                ulonglong2 va = *reinterpret_cast<const ulonglong2*>(vr);
                ulonglong2 vb = *reinterpret_cast<const ulonglong2*>(vr + 2);
                ull vp[4]; vp[0] = va.x; vp[1] = va.y; vp[2] = vb.x; vp[3] = vb.y;
#pragma unroll
                for (int ii = 0; ii < 4; ++ii) {
                    acc[ii][0] = fma2(at2.x, vp[ii], acc[ii][0]);
                    acc[ii][1] = fma2(at2.y, vp[ii], acc[ii][1]);
                    const int o0 = 3 - jj;          // p = 0
                    const int o1 = 5 - jj;          // p = 1
                    ull pr0 = (o0 & 1) ? wo[ii][o0 >> 1] : we[ii][o0 >> 1];
                    ull pr1 = (o1 & 1) ? wo[ii][o1 >> 1] : we[ii][o1 >> 1];
                    acc[ii][0] = fma2(at2.x, pr0, acc[ii][0]);
                    acc[ii][1] = fma2(at2.y, pr1, acc[ii][1]);
                }
            }
        }

        __syncthreads();           // all attnT reads done
        ull* red = reinterpret_cast<ull*>(attnT);   // 16 KB alias, 1024 ull used

        if (jh == 1) {
#pragma unroll
            for (int ii = 0; ii < 4; ++ii) {
                red[(i0 + ii) * 64 + lane * 2 + 0] = acc[ii][0];
                red[(i0 + ii) * 64 + lane * 2 + 1] = acc[ii][1];
            }
        }
        __syncthreads();

        if (jh == 0) {
            float4 iv4 = *reinterpret_cast<const float4*>(invs + d0);
            float* ob = out + (size_t)b * 16384 + h * 2048;
#pragma unroll
            for (int ii = 0; ii < 4; ++ii) {
                ull s0 = add2(acc[ii][0], red[(i0 + ii) * 64 + lane * 2 + 0]);
                ull s1 = add2(acc[ii][1], red[(i0 + ii) * 64 + lane * 2 + 1]);
                float4 r;
                upk2(s0, r.x, r.y);
                upk2(s1, r.z, r.w);
                r.x *= iv4.x; r.y *= iv4.y; r.z *= iv4.z; r.w *= iv4.w;
                *reinterpret_cast<float4*>(ob + (i0 + ii) * 128 + d0) = r;
            }
        }
    }
}

// ============================================================================
extern "C" void kernel_launch(void* const* d_in, const int* in_sizes, int n_in,
                              void* d_out, int out_size) {
    const float* x        = (const float*)d_in[0];
    const float* W        = (const float*)d_in[1];
    const float* gamma    = (const float*)d_in[2];
    const float* beta     = (const float*)d_in[3];
    const float* mean     = (const float*)d_in[4];
    const float* var      = (const float*)d_in[5];
    const float* relative = (const float*)d_in[6];
    float* out = (float*)d_out;

    int nb = in_sizes[0] / (INC * DIM);

    float* scratch;
    cudaGetSymbolAddress((void**)&scratch, g_qkv);

    const int smemA = (32 * AS_STRIDE + 32 * 128) * (int)sizeof(float);
    const int smemB = SM_TOTAL * (int)sizeof(float);
    cudaFuncSetAttribute(conv_bn_kernel, cudaFuncAttributeMaxDynamicSharedMemorySize, smemA);
    cudaFuncSetAttribute(attn_kernel,    cudaFuncAttributeMaxDynamicSharedMemorySize, smemB);

    conv_bn_kernel<<<nb, 512, smemA>>>(x, W, gamma, beta, mean, var, scratch);
    attn_kernel<<<nb * HEADS, 256, smemB>>>(scratch, relative, out);
}

// round 6
// speedup vs baseline: 1.3980x; 1.2099x over previous
#include <cuda_runtime.h>
#include <math.h>
#include <stdint.h>

#define HEADS 8
#define DHK 8
#define DHV 16
#define DIM 128
#define INC 128
#define EPS 1e-5f
#define QSCALE 0.08838834764831845f   // 128^-0.5

typedef unsigned long long ull;

__device__ float g_qkv[2048 * 32768];   // [b][h][r(0..31)][d]

__device__ __forceinline__ ull pk2(float a, float b) {
    ull r; asm("mov.b64 %0, {%1, %2};" : "=l"(r) : "f"(a), "f"(b)); return r;
}
__device__ __forceinline__ void upk2(ull v, float& a, float& b) {
    asm("mov.b64 {%0, %1}, %2;" : "=f"(a), "=f"(b) : "l"(v));
}
__device__ __forceinline__ ull fma2(ull a, ull b, ull c) {
    ull r; asm("fma.rn.f32x2 %0, %1, %2, %3;" : "=l"(r) : "l"(a), "l"(b), "l"(c));
    return r;
}
__device__ __forceinline__ ull add2(ull a, ull b) {
    ull r; asm("add.rn.f32x2 %0, %1, %2;" : "=l"(r) : "l"(a), "l"(b));
    return r;
}
__device__ __forceinline__ uint32_t f2tf32(float f) {
    uint32_t r; asm("cvt.rna.tf32.f32 %0, %1;" : "=r"(r) : "f"(f)); return r;
}
__device__ __forceinline__ void mma_tf32(float* c, const uint32_t* a, const uint32_t* b) {
    asm volatile(
        "mma.sync.aligned.m16n8k8.row.col.f32.tf32.tf32.f32 "
        "{%0,%1,%2,%3}, {%4,%5,%6,%7}, {%8,%9}, {%0,%1,%2,%3};"
        : "+f"(c[0]), "+f"(c[1]), "+f"(c[2]), "+f"(c[3])
        : "r"(a[0]), "r"(a[1]), "r"(a[2]), "r"(a[3]), "r"(b[0]), "r"(b[1]));
}

// ============================================================================
// Kernel A: conv1x1 + BN via mma.sync tf32 (HMMA).
//   C[o][d] = sum_c W[o][c] * x[b][c][d]
//   A = W (row-major m=o, k=c), B = x (k=c rows, n=d cols, natural layout).
// 2 CTAs per batch (o halves of 128). 8 warps, warp tile 32(M) x 64(N).
// smem floats: As[128][132] @0, Bs[128][136] @16896, ivs @34304, bss @34432.
// ============================================================================
#define CA_STR 132
#define CB_STR 136
#define CV_BS  (128 * CA_STR)          // 16896
#define CV_IV  (CV_BS + 128 * CB_STR)  // 34304
#define CV_BB  (CV_IV + 128)           // 34432
#define CV_TOT (CV_BB + 128)           // 34560 floats = 138240 B

__global__ void __launch_bounds__(256, 1)
conv_bn_mma_kernel(const float* __restrict__ x, const float* __restrict__ W,
                   const float* __restrict__ gamma, const float* __restrict__ beta,
                   const float* __restrict__ mean, const float* __restrict__ var,
                   float* __restrict__ qkv)
{
    extern __shared__ float sm[];
    float* As  = sm;
    float* Bs  = sm + CV_BS;
    float* ivs = sm + CV_IV;
    float* bss = sm + CV_BB;

    const int t      = threadIdx.x;
    const int b      = blockIdx.x >> 1;
    const int o_base = (blockIdx.x & 1) * 128;

    // ---- stage W half (tf32-rounded) ----------------------------------------
#pragma unroll
    for (int it = 0; it < 16; ++it) {
        int e  = t + 256 * it;            // 0..4095 float4 groups
        int o  = e >> 5;
        int c4 = (e & 31) * 4;
        float4 wv = *reinterpret_cast<const float4*>(W + (o_base + o) * 128 + c4);
        float4 s;
        s.x = __uint_as_float(f2tf32(wv.x));
        s.y = __uint_as_float(f2tf32(wv.y));
        s.z = __uint_as_float(f2tf32(wv.z));
        s.w = __uint_as_float(f2tf32(wv.w));
        *reinterpret_cast<float4*>(As + o * CA_STR + c4) = s;
    }
    // ---- stage x tile (natural [c][d] layout, tf32-rounded) ------------------
#pragma unroll
    for (int it = 0; it < 16; ++it) {
        int e  = t + 256 * it;
        int c  = e >> 5;
        int d4 = (e & 31) * 4;
        float4 xv = *reinterpret_cast<const float4*>(x + (size_t)b * 16384 + c * 128 + d4);
        float4 s;
        s.x = __uint_as_float(f2tf32(xv.x));
        s.y = __uint_as_float(f2tf32(xv.y));
        s.z = __uint_as_float(f2tf32(xv.z));
        s.w = __uint_as_float(f2tf32(xv.w));
        *reinterpret_cast<float4*>(Bs + c * CB_STR + d4) = s;
    }
    // ---- BN coefficients ------------------------------------------------------
    if (t < 128) {
        int o = o_base + t;
        float iv   = gamma[o] * rsqrtf(var[o] + EPS);
        float bias = beta[o] - mean[o] * iv;
        if (o < 64) { iv *= QSCALE; bias *= QSCALE; }
        ivs[t] = iv;
        bss[t] = bias;
    }
    __syncthreads();

    // ---- main MMA loop ---------------------------------------------------------
    const int warp = t >> 5, lane = t & 31;
    const int wm = warp & 3, wn = warp >> 2;
    const int m0 = wm * 32, n0 = wn * 64;
    const int gp = lane >> 2, tid4 = lane & 3;

    float acc[16][4];
#pragma unroll
    for (int i = 0; i < 16; ++i)
#pragma unroll
        for (int p = 0; p < 4; ++p) acc[i][p] = 0.f;

#pragma unroll
    for (int s = 0; s < 16; ++s) {
        uint32_t a[2][4];
        const float* abase = As + s * 8 + tid4;
#pragma unroll
        for (int mt = 0; mt < 2; ++mt) {
            int r0 = m0 + mt * 16 + gp;
            a[mt][0] = __float_as_uint(abase[r0 * CA_STR]);
            a[mt][1] = __float_as_uint(abase[(r0 + 8) * CA_STR]);
            a[mt][2] = __float_as_uint(abase[r0 * CA_STR + 4]);
            a[mt][3] = __float_as_uint(abase[(r0 + 8) * CA_STR + 4]);
        }
        uint32_t bf[8][2];
        const float* bbase = Bs + (s * 8 + tid4) * CB_STR + n0 + gp;
#pragma unroll
        for (int nt = 0; nt < 8; ++nt) {
            bf[nt][0] = __float_as_uint(bbase[nt * 8]);
            bf[nt][1] = __float_as_uint(bbase[4 * CB_STR + nt * 8]);
        }
#pragma unroll
        for (int mt = 0; mt < 2; ++mt)
#pragma unroll
            for (int nt = 0; nt < 8; ++nt)
                mma_tf32(acc[mt * 8 + nt], a[mt], bf[nt]);
    }

    // ---- epilogue: BN + store to g_qkv ------------------------------------------
#pragma unroll
    for (int mt = 0; mt < 2; ++mt) {
        int lr0 = m0 + mt * 16 + gp;
        int lr1 = lr0 + 8;
        float iv0 = ivs[lr0], bv0 = bss[lr0];
        float iv1 = ivs[lr1], bv1 = bss[lr1];
        int o0 = o_base + lr0, o1 = o_base + lr1;
        float* d00 = qkv + (size_t)b * 32768 + (o0 & 7) * 4096 + (o0 >> 3) * 128;
        float* d01 = qkv + (size_t)b * 32768 + (o1 & 7) * 4096 + (o1 >> 3) * 128;
#pragma unroll
        for (int nt = 0; nt < 8; ++nt) {
            int d = n0 + nt * 8 + 2 * tid4;
            const float* a4 = acc[mt * 8 + nt];
            float2 s0, s1;
            s0.x = a4[0] * iv0 + bv0; s0.y = a4[1] * iv0 + bv0;
            s1.x = a4[2] * iv1 + bv1; s1.y = a4[3] * iv1 + bv1;
            *reinterpret_cast<float2*>(d00 + d) = s0;
            *reinterpret_cast<float2*>(d01 + d) = s1;
        }
    }
}

// ============================================================================
// Kernel B: attention per (b, h) — unchanged (round-4 best)
// ============================================================================
#define AT_STRIDE 132
#define SM_Q     0
#define SM_K     1024
#define SM_VDUP  2048
#define SM_REL   6144
#define SM_ATT   10240
#define SM_INV   27136
#define SM_TOTAL 27264

__global__ void __launch_bounds__(256, 2)
attn_kernel(const float* __restrict__ qkv, const float* __restrict__ relative,
            float* __restrict__ out)
{
    extern __shared__ float sm[];
    float* q     = sm + SM_Q;
    float* k     = sm + SM_K;
    ull*   vdup  = reinterpret_cast<ull*>(sm + SM_VDUP);
    float* relqk = sm + SM_REL;
    float* attnT = sm + SM_ATT;
    float* invs  = sm + SM_INV;
    float* psum  = sm + SM_Q;
    float* relv  = relqk;

    const int t   = threadIdx.x;
    const int bid = blockIdx.x;
    const int b   = bid >> 3;
    const int h   = bid & 7;

    {
        const float* src = qkv + (size_t)b * 32768 + h * 4096;
#pragma unroll
        for (int it = 0; it < 4; ++it) {
            int e4 = t + 256 * it;
            int r  = e4 >> 5;
            int dw = (e4 & 31) * 4;
            float4 val = *reinterpret_cast<const float4*>(src + r * 128 + dw);
            if (r < 8) {
                *reinterpret_cast<float4*>(q + r * 128 + dw) = val;
            } else if (r < 16) {
                *reinterpret_cast<float4*>(k + (r - 8) * 128 + dw) = val;
            } else {
                int i = r - 16;
                vdup[(dw + 0) * 16 + i] = pk2(val.x, val.x);
                vdup[(dw + 1) * 16 + i] = pk2(val.y, val.y);
                vdup[(dw + 2) * 16 + i] = pk2(val.z, val.z);
                vdup[(dw + 3) * 16 + i] = pk2(val.w, val.w);
            }
        }
        for (int idx = t; idx < 16 * 255; idx += 256) {
            int c = idx / 255, m = idx - c * 255;
            relqk[c * 256 + m] = relative[idx];
        }
    }
    __syncthreads();

    float sums[8];
    {
        const int tx = t & 15, ty = t >> 4;
        const int d0 = tx * 8, j0 = ty * 8;
        const int base = d0 - j0 + 120;

        ull acc[8][4];
#pragma unroll
        for (int a = 0; a < 8; ++a)
#pragma unroll
            for (int p = 0; p < 4; ++p) acc[a][p] = 0ULL;

#pragma unroll 2
        for (int i = 0; i < 8; ++i) {
            const float* qi = q + i * 128;
            const float* ki = k + i * 128;
            ull qp[4], kp[4];
            {
                ulonglong2 a0 = *reinterpret_cast<const ulonglong2*>(qi + d0);
                ulonglong2 a1 = *reinterpret_cast<const ulonglong2*>(qi + d0 + 4);
                qp[0] = a0.x; qp[1] = a0.y; qp[2] = a1.x; qp[3] = a1.y;
                ulonglong2 b0 = *reinterpret_cast<const ulonglong2*>(ki + d0);
                ulonglong2 b1 = *reinterpret_cast<const ulonglong2*>(ki + d0 + 4);
                kp[0] = b0.x; kp[1] = b0.y; kp[2] = b1.x; kp[3] = b1.y;
            }
            {
                float kj[8];
                *reinterpret_cast<float4*>(kj)     = *reinterpret_cast<const float4*>(ki + j0);
                *reinterpret_cast<float4*>(kj + 4) = *reinterpret_cast<const float4*>(ki + j0 + 4);
#pragma unroll
                for (int jj = 0; jj < 8; ++jj) {
                    ull kk2 = pk2(kj[jj], kj[jj]);
#pragma unroll
                    for (int p = 0; p < 4; ++p)
                        acc[jj][p] = fma2(qp[p], kk2, acc[jj][p]);
                }
            }
            {
                float wv[16];
                const float* rr = relqk + i * 256 + base;
#pragma unroll
                for (int u = 0; u < 4; ++u)
                    *reinterpret_cast<float4*>(wv + 4 * u) = *reinterpret_cast<const float4*>(rr + 4 * u);
                ull wo[7];
#pragma unroll
                for (int u = 0; u < 7; ++u) wo[u] = pk2(wv[2 * u + 1], wv[2 * u + 2]);
#pragma unroll
                for (int jj = 0; jj < 8; ++jj)
#pragma unroll
                    for (int p = 0; p < 4; ++p) {
                        const int a = 2 * p + 7 - jj;
                        ull pair = (a & 1) ? wo[a >> 1]
                                           : *reinterpret_cast<const ull*>(wv + a);
                        acc[jj][p] = fma2(qp[p], pair, acc[jj][p]);
                    }
            }
            {
                float wv[16];
                const float* rr = relqk + (8 + i) * 256 + base;
#pragma unroll
                for (int u = 0; u < 4; ++u)
                    *reinterpret_cast<float4*>(wv + 4 * u) = *reinterpret_cast<const float4*>(rr + 4 * u);
                ull wo[7];
#pragma unroll
                for (int u = 0; u < 7; ++u) wo[u] = pk2(wv[2 * u + 1], wv[2 * u + 2]);
#pragma unroll
                for (int jj = 0; jj < 8; ++jj)
#pragma unroll
                    for (int p = 0; p < 4; ++p) {
                        const int a = 2 * p + 7 - jj;
                        ull pair = (a & 1) ? wo[a >> 1]
                                           : *reinterpret_cast<const ull*>(wv + a);
                        acc[jj][p] = fma2(kp[p], pair, acc[jj][p]);
                    }
            }
        }

#pragma unroll
        for (int dd = 0; dd < 8; ++dd) sums[dd] = 0.f;
#pragma unroll
        for (int jj = 0; jj < 8; ++jj) {
            float* dst = attnT + (j0 + jj) * AT_STRIDE + d0;
#pragma unroll
            for (int p = 0; p < 4; ++p) {
                float lo, hi;
                upk2(acc[jj][p], lo, hi);
                float e0 = __expf(lo), e1 = __expf(hi);
                sums[2 * p]     += e0;
                sums[2 * p + 1] += e1;
                float2 s; s.x = e0; s.y = e1;
                *reinterpret_cast<float2*>(dst + 2 * p) = s;
            }
        }
    }
    __syncthreads();

    {
        const int tx = t & 15, ty = t >> 4;
        const int d0 = tx * 8;
#pragma unroll
        for (int dd = 0; dd < 8; ++dd)
            psum[ty * 128 + d0 + dd] = sums[dd];
        for (int idx = t; idx < 16 * 255; idx += 256) {
            int c = idx / 255, m = idx - c * 255;
            relv[c * 256 + m] = relative[16 * 255 + idx];
        }
    }
    __syncthreads();
    if (t < 128) {
        float s = 0.f;
#pragma unroll
        for (int ty2 = 0; ty2 < 16; ++ty2) s += psum[ty2 * 128 + t];
        invs[t] = 1.0f / s;
    }
    __syncthreads();

    {
        const int lane = t & 31;
        const int wd   = t >> 5;
        const int i0   = (wd & 3) * 4;
        const int jh   = wd >> 2;
        const int d0   = lane * 4;
        const int jb0  = jh * 64;

        ull acc[4][2];
#pragma unroll
        for (int ii = 0; ii < 4; ++ii) { acc[ii][0] = 0ULL; acc[ii][1] = 0ULL; }

        ull we[4][3], wo[4][3];
        float lastf0[4];

#pragma unroll
        for (int ii = 0; ii < 4; ++ii) {
            const float* rp = relv + (i0 + ii) * 256 + (d0 - jb0 + 124);
            float4 lo4 = *reinterpret_cast<const float4*>(rp);
            float4 hi4 = *reinterpret_cast<const float4*>(rp + 4);
            we[ii][0] = pk2(lo4.x, lo4.y);
            we[ii][1] = pk2(lo4.z, lo4.w);
            we[ii][2] = pk2(hi4.x, hi4.y);
            wo[ii][0] = pk2(lo4.y, lo4.z);
            wo[ii][1] = pk2(lo4.w, hi4.x);
            wo[ii][2] = pk2(hi4.y, hi4.z);
            lastf0[ii] = lo4.x;
        }

        for (int g = 0; g < 16; ++g) {
            const int jb = jb0 + g * 4;
            if (g > 0) {
                const int baseg = d0 - jb + 124;
#pragma unroll
                for (int ii = 0; ii < 4; ++ii) {
                    we[ii][2] = we[ii][0];
                    wo[ii][2] = wo[ii][0];
                    float4 f = *reinterpret_cast<const float4*>(relv + (i0 + ii) * 256 + baseg);
                    we[ii][0] = pk2(f.x, f.y);
                    we[ii][1] = pk2(f.z, f.w);
                    wo[ii][0] = pk2(f.y, f.z);
                    wo[ii][1] = pk2(f.w, lastf0[ii]);
                    lastf0[ii] = f.x;
                }
            }
#pragma unroll
            for (int jj = 0; jj < 4; ++jj) {
                const int j = jb + jj;
                ulonglong2 at2 = *reinterpret_cast<const ulonglong2*>(attnT + j * AT_STRIDE + d0);
                const ull* vr = vdup + j * 16 + i0;
                ulonglong2 va = *reinterpret_cast<const ulonglong2*>(vr);
                ulonglong2 vb = *reinterpret_cast<const ulonglong2*>(vr + 2);
                ull vp[4]; vp[0] = va.x; vp[1] = va.y; vp[2] = vb.x; vp[3] = vb.y;
#pragma unroll
                for (int ii = 0; ii < 4; ++ii) {
                    acc[ii][0] = fma2(at2.x, vp[ii], acc[ii][0]);
                    acc[ii][1] = fma2(at2.y, vp[ii], acc[ii][1]);
                    const int o0 = 3 - jj;
                    const int o1 = 5 - jj;
                    ull pr0 = (o0 & 1) ? wo[ii][o0 >> 1] : we[ii][o0 >> 1];
                    ull pr1 = (o1 & 1) ? wo[ii][o1 >> 1] : we[ii][o1 >> 1];
                    acc[ii][0] = fma2(at2.x, pr0, acc[ii][0]);
                    acc[ii][1] = fma2(at2.y, pr1, acc[ii][1]);
                }
            }
        }

        __syncthreads();
        ull* red = reinterpret_cast<ull*>(attnT);

        if (jh == 1) {
#pragma unroll
            for (int ii = 0; ii < 4; ++ii) {
                red[(i0 + ii) * 64 + lane * 2 + 0] = acc[ii][0];
                red[(i0 + ii) * 64 + lane * 2 + 1] = acc[ii][1];
            }
        }
        __syncthreads();

        if (jh == 0) {
            float4 iv4 = *reinterpret_cast<const float4*>(invs + d0);
            float* ob = out + (size_t)b * 16384 + h * 2048;
#pragma unroll
            for (int ii = 0; ii < 4; ++ii) {
                ull s0 = add2(acc[ii][0], red[(i0 + ii) * 64 + lane * 2 + 0]);
                ull s1 = add2(acc[ii][1], red[(i0 + ii) * 64 + lane * 2 + 1]);
                float4 r;
                upk2(s0, r.x, r.y);
                upk2(s1, r.z, r.w);
                r.x *= iv4.x; r.y *= iv4.y; r.z *= iv4.z; r.w *= iv4.w;
                *reinterpret_cast<float4*>(ob + (i0 + ii) * 128 + d0) = r;
            }
        }
    }
}

// ============================================================================
extern "C" void kernel_launch(void* const* d_in, const int* in_sizes, int n_in,
                              void* d_out, int out_size) {
    const float* x        = (const float*)d_in[0];
    const float* W        = (const float*)d_in[1];
    const float* gamma    = (const float*)d_in[2];
    const float* beta     = (const float*)d_in[3];
    const float* mean     = (const float*)d_in[4];
    const float* var      = (const float*)d_in[5];
    const float* relative = (const float*)d_in[6];
    float* out = (float*)d_out;

    int nb = in_sizes[0] / (INC * DIM);

    float* scratch;
    cudaGetSymbolAddress((void**)&scratch, g_qkv);

    const int smemA = CV_TOT * (int)sizeof(float);     // 138240
    const int smemB = SM_TOTAL * (int)sizeof(float);   // 109056
    cudaFuncSetAttribute(conv_bn_mma_kernel, cudaFuncAttributeMaxDynamicSharedMemorySize, smemA);
    cudaFuncSetAttribute(attn_kernel,        cudaFuncAttributeMaxDynamicSharedMemorySize, smemB);

    conv_bn_mma_kernel<<<nb * 2, 256, smemA>>>(x, W, gamma, beta, mean, var, scratch);
    attn_kernel<<<nb * HEADS, 256, smemB>>>(scratch, relative, out);
}